// round 8
// baseline (speedup 1.0000x reference)
#include <cuda_runtime.h>
#include <cuda_fp16.h>
#include <cstdint>

// y[m,n] = mask[m] ? x[m,:]·W_v[n,:] : x[m,:]·W_t[n,:]
// Mask-partitioned single GEMM, fp16 m16n8k16 mma.sync, fp32 accumulate.
// A path fused: gathered fp32 LDG (1 iter ahead) -> fp16 convert -> STS into
// fragment-order layout (consumer LDS path identical to the fast R4 kernel).
// B: fragment-order fp16 panels via cp.async (prepass k4). No k3 prepass.

#define M_TOTAL 32768
#define K_DIM   1024
#define N_DIM   1024
#define BM 128
#define BN 128
#define BK 32
#define NK (K_DIM / BK)              // 32 k-panels
#define THREADS 128
#define M_PAD 32896                  // 257 tiles * 128
#define NMT (M_PAD / BM)             // 257

#define PANEL_H  4096                // halves per 8KB B panel (128n x 32k)
#define BPANEL_B 8192
#define ABLK_B   576                 // A frag-block stride (512+64: bank skew)
#define A_STAGE  (16 * ABLK_B)       // 9216
#define STAGE_B  (A_STAGE + BPANEL_B)// 17408
#define STAGES   3
#define DYN_SMEM (STAGES * STAGE_B)  // 52224

// ------------------------------------------------------------- device state
__device__ __half g_wv[(size_t)N_DIM * K_DIM];   // [ntile][kpanel][frag order]
__device__ __half g_wt[(size_t)N_DIM * K_DIM];
__device__ int   g_perm[M_PAD];                  // slot -> source row (-1 dead)
__device__ int   g_nv, g_cv, g_ct;
__device__ int   g_mask_is_u8;

// ------------------------------------------------------------- helpers
__device__ __forceinline__ bool mask_at(const unsigned char* m, int i) {
    return g_mask_is_u8 ? (m[i] != 0) : (((const int*)m)[i] != 0);
}

__device__ __forceinline__ uint32_t smem_u32(const void* p) {
    uint32_t a;
    asm("{ .reg .u64 t; cvta.to.shared.u64 t, %1; cvt.u32.u64 %0, t; }"
        : "=r"(a) : "l"(p));
    return a;
}

__device__ __forceinline__ void cp16(uint32_t saddr, const void* g) {
    asm volatile("cp.async.cg.shared.global [%0], [%1], 16;"
                 :: "r"(saddr), "l"(g) : "memory");
}

__device__ __forceinline__ void mma_f16(float* d, const uint32_t* a, const uint32_t* b) {
    asm volatile(
        "mma.sync.aligned.m16n8k16.row.col.f32.f16.f16.f32 "
        "{%0,%1,%2,%3}, {%4,%5,%6,%7}, {%8,%9}, {%0,%1,%2,%3};"
        : "+f"(d[0]), "+f"(d[1]), "+f"(d[2]), "+f"(d[3])
        : "r"(a[0]), "r"(a[1]), "r"(a[2]), "r"(a[3]), "r"(b[0]), "r"(b[1]));
}

__device__ __forceinline__ uint32_t packh2(float lo, float hi) {
    __half2 h = __float22half2_rn(make_float2(lo, hi));
    return *(uint32_t*)&h;
}

// ------------------------------------------------------------- prep kernels
__global__ void k0_init(const unsigned char* __restrict__ m) {
    int tid = threadIdx.x;
    int gi = blockIdx.x * 1024 + tid;
    if (gi < M_PAD) g_perm[gi] = -1;
    if (blockIdx.x == 0) {
        __shared__ int found;
        if (tid == 0) { found = 0; g_nv = 0; g_cv = 0; g_ct = 0; }
        __syncthreads();
        int local = 0;
        for (int i = tid; i < 8192; i += 1024)
            if (m[4 * i + 1] | m[4 * i + 2] | m[4 * i + 3]) local = 1;
        if (local) atomicOr(&found, 1);
        __syncthreads();
        if (tid == 0) g_mask_is_u8 = found;
    }
}

__global__ void k1_count(const unsigned char* __restrict__ m) {
    int row = blockIdx.x * 256 + threadIdx.x;
    bool mv = mask_at(m, row);
    unsigned bal = __ballot_sync(0xffffffffu, mv);
    if ((threadIdx.x & 31) == 0) atomicAdd(&g_nv, __popc(bal));
}

__global__ void k2_assign(const unsigned char* __restrict__ m) {
    __shared__ int s_v[8], s_t[8];
    __shared__ int s_baseV, s_baseT;
    int tid = threadIdx.x;
    int row = blockIdx.x * 256 + tid;
    int warp = tid >> 5, lane = tid & 31;
    bool mv = mask_at(m, row);
    unsigned bal = __ballot_sync(0xffffffffu, mv);
    int lpv = __popc(bal & ((1u << lane) - 1));
    int lpt = lane - lpv;
    if (lane == 0) { s_v[warp] = __popc(bal); s_t[warp] = 32 - __popc(bal); }
    __syncthreads();
    if (tid == 0) {
        int av = 0, at = 0;
        #pragma unroll
        for (int w = 0; w < 8; w++) {
            int tv = s_v[w]; s_v[w] = av; av += tv;
            int tt = s_t[w]; s_t[w] = at; at += tt;
        }
        s_baseV = atomicAdd(&g_cv, av);
        s_baseT = atomicAdd(&g_ct, at);
    }
    __syncthreads();
    int pad = (g_nv + 127) & ~127;
    int slot = mv ? (s_baseV + s_v[warp] + lpv)
                  : (pad + s_baseT + s_t[warp] + lpt);
    g_perm[slot] = row;
}

// K4: one weight matrix -> fp16 B panels in fragment order (launched twice).
__global__ void k4_wconv(const float* __restrict__ W, int which) {
    const int nt = blockIdx.x, kp = blockIdx.y;
    __half* dst = (which ? g_wt : g_wv) + ((size_t)nt * NK + kp) * PANEL_H;
    const int tid = threadIdx.x;
    const int kbase = kp * BK;

    #pragma unroll
    for (int q = 0; q < 2; q++) {
        int h0 = tid * 8 + q * 2048;
        __half vals[8];
        #pragma unroll
        for (int j = 0; j < 8; j++) {
            int h = h0 + j;
            int b = h >> 7;
            int nb = b >> 1, ks = b & 1;
            int lane = (h >> 2) & 31;
            int v = h & 3;
            int grp = lane >> 2, qid = lane & 3;
            int n = nt * 128 + nb * 8 + grp;
            int k = kbase + ks * 16 + 2 * qid + 8 * (v >> 1) + (v & 1);
            vals[j] = __float2half_rn(W[(size_t)n * K_DIM + k]);
        }
        *(uint4*)(dst + h0) = *(const uint4*)vals;
    }
}

// ------------------------------------------------------------- GEMM
extern __shared__ __align__(128) char dsmem[];

__global__ __launch_bounds__(THREADS, 2)
void gemm_kernel(const float* __restrict__ x, float* __restrict__ out)
{
    const int tid  = threadIdx.x;
    const int warp = tid >> 5;
    const int lane = tid & 31;
    const int grp  = lane >> 2;
    const int qid  = lane & 3;
    const int rb0  = (warp >> 1) * 4;        // A block base (64 rows)
    const int nb0  = (warp & 1) * 8;         // B block base (64 cols)
    const int blockN = blockIdx.x * BN;
    const int mt     = blockIdx.y;
    const int blockM = mt * BM;

    const int pad = (g_nv + 127) & ~127;
    const char* gB = (const char*)(((blockM < pad) ? g_wv : g_wt)
                                   + (size_t)blockIdx.x * NK * PANEL_H);

    const uint32_t sbase = smem_u32(dsmem);

    // per-thread A chunks: chunk c = i*128 + tid -> row c>>3, k-quad c&7
    uint32_t aoff[8];      // fp32 element offset into x
    uint32_t sts_off[8];   // within-stage byte offset of pack0
    #pragma unroll
    for (int i = 0; i < 8; i++) {
        int c = i * 128 + tid;
        int r = c >> 3, kc4 = c & 7;
        int src = g_perm[blockM + r];
        if (src < 0) src = 0;                 // dead row: any valid source
        aoff[i] = (uint32_t)src * K_DIM + kc4 * 4;
        int rb = r >> 4, rg = r & 7, rh = (r >> 3) & 1;
        int ks = kc4 >> 2, rk = (kc4 >> 1) & 1, qb = (kc4 & 1) * 2;
        sts_off[i] = (uint32_t)((rb * 2 + ks) * ABLK_B
                                + (rg * 4 + qb) * 16 + (4 * rk + 2 * rh) * 2);
    }

    float acc[4][8][4];
    #pragma unroll
    for (int i = 0; i < 4; i++)
        #pragma unroll
        for (int j = 0; j < 8; j++)
            #pragma unroll
            for (int c = 0; c < 4; c++) acc[i][j][c] = 0.f;

    float4 ra[8];   // A prefetch registers (one k-panel)

    auto ALDG = [&](int kt) {
        #pragma unroll
        for (int i = 0; i < 8; i++)
            ra[i] = *(const float4*)(x + aoff[i] + kt * BK);
    };

    auto ASTS = [&](int kt) {
        const uint32_t sa = sbase + (kt % STAGES) * STAGE_B;
        #pragma unroll
        for (int i = 0; i < 8; i++) {
            uint32_t p0 = packh2(ra[i].x, ra[i].y);
            uint32_t p1 = packh2(ra[i].z, ra[i].w);
            uint32_t ad = sa + sts_off[i];
            asm volatile("st.shared.b32 [%0], %1;" :: "r"(ad), "r"(p0) : "memory");
            asm volatile("st.shared.b32 [%0], %1;" :: "r"(ad + 16), "r"(p1) : "memory");
        }
    };

    auto BISSUE = [&](int kt) {
        const uint32_t sst = sbase + (kt % STAGES) * STAGE_B + A_STAGE;
        const char* srcB = gB + (size_t)kt * BPANEL_B;
        #pragma unroll
        for (int i = 0; i < 4; i++) {
            uint32_t off = (uint32_t)(i * 2048 + tid * 16);
            cp16(sst + off, srcB + off);
        }
        asm volatile("cp.async.commit_group;" ::: "memory");
    };

    // prologue
    ALDG(0); ASTS(0); ALDG(1);
    BISSUE(0); BISSUE(1);

    for (int kt = 0; kt < NK; kt++) {
        if (kt + 1 < NK)
            asm volatile("cp.async.wait_group 1;" ::: "memory");
        else
            asm volatile("cp.async.wait_group 0;" ::: "memory");
        __syncthreads();    // A(kt) STS + B(kt) cp.async now visible/complete

        if (kt + 1 < NK) ASTS(kt + 1);                 // from ra
        if (kt + 2 < NK) { ALDG(kt + 2); BISSUE(kt + 2); }

        const char* stage = dsmem + (kt % STAGES) * STAGE_B;
        const char* sB = stage + A_STAGE;

        #pragma unroll
        for (int ks = 0; ks < 2; ks++) {
            uint32_t a[4][4];
            #pragma unroll
            for (int i = 0; i < 4; i++) {
                uint4 v = *(const uint4*)(stage + ((rb0 + i) * 2 + ks) * ABLK_B
                                          + lane * 16);
                a[i][0] = v.x; a[i][1] = v.y; a[i][2] = v.z; a[i][3] = v.w;
            }
            uint32_t b[8][2];
            #pragma unroll
            for (int j = 0; j < 8; j++) {
                uint2 v = *(const uint2*)(sB + ((nb0 + j) * 2 + ks) * 256 + lane * 8);
                b[j][0] = v.x; b[j][1] = v.y;
            }
            #pragma unroll
            for (int i = 0; i < 4; i++)
                #pragma unroll
                for (int j = 0; j < 8; j++)
                    mma_f16(acc[i][j], a[i], b[j]);
        }
    }

    // epilogue: scatter rows through perm
    #pragma unroll
    for (int i = 0; i < 4; i++) {
        int r = rb0 * 16 + i * 16 + grp;
        int d0 = g_perm[blockM + r];
        int d1 = g_perm[blockM + r + 8];
        #pragma unroll
        for (int j = 0; j < 8; j++) {
            int col = blockN + nb0 * 8 + j * 8 + qid * 2;
            if (d0 >= 0)
                *(float2*)(out + (size_t)d0 * N_DIM + col) =
                    make_float2(acc[i][j][0], acc[i][j][1]);
            if (d1 >= 0)
                *(float2*)(out + (size_t)d1 * N_DIM + col) =
                    make_float2(acc[i][j][2], acc[i][j][3]);
        }
    }
}

// ------------------------------------------------------------- launch
extern "C" void kernel_launch(void* const* d_in, const int* in_sizes, int n_in,
                              void* d_out, int out_size)
{
    const float*         x    = (const float*)d_in[0];
    const unsigned char* mask = (const unsigned char*)d_in[1];
    const float*         Wv   = (const float*)d_in[2];
    const float*         Wt   = (const float*)d_in[3];
    float*               out  = (float*)d_out;

    static bool attr_set = false;
    if (!attr_set) {
        cudaFuncSetAttribute(gemm_kernel,
                             cudaFuncAttributeMaxDynamicSharedMemorySize, DYN_SMEM);
        attr_set = true;
    }

    // 6 launches/call with the GEMM last -> ncu (-s 5 -c 1) profiles the GEMM
    k0_init<<<(M_PAD + 1023) / 1024, 1024>>>(mask);
    k1_count<<<M_TOTAL / 256, 256>>>(mask);
    k2_assign<<<M_TOTAL / 256, 256>>>(mask);
    k4_wconv<<<dim3(N_DIM / 128, NK), 256>>>(Wv, 0);
    k4_wconv<<<dim3(N_DIM / 128, NK), 256>>>(Wt, 1);
    gemm_kernel<<<dim3(N_DIM / BN, NMT), THREADS, DYN_SMEM>>>(x, out);
}